// round 1
// baseline (speedup 1.0000x reference)
#include <cuda_runtime.h>
#include <cuda_bf16.h>
#include <math.h>

// Problem constants
#define BB   8
#define TT   4096
#define DD   256
#define MM   8
#define CHUNK 32
#define NC   (TT / CHUNK)      // 128 chunks along T
#define D4   (DD / 4)          // 64 float4 groups per row
#define RPB  (MM * D4)         // 512 float4 "r" slots per (b,c)

// Scratch (static device allocations — no runtime alloc)
__device__ float g_L[(size_t)BB * NC * MM * DD];   // chunk-local final states, 8 MB
__device__ float g_S[(size_t)BB * NC * MM * DD];   // chunk initial states,     8 MB
__device__ float g_A[BB * NC * MM];                // chunk decay products

// ---------------------------------------------------------------------------
// Kernel 1: per-chunk local recurrence (s starts at 0), store L and A.
// Block = (b, c). 64 threads, each owns 4 consecutive d's for all 8 m's.
// ---------------------------------------------------------------------------
__global__ __launch_bounds__(64) void k_locals(
    const float* __restrict__ x, const float* __restrict__ delta,
    const float* __restrict__ tau)
{
    int blk = blockIdx.x;
    int b = blk >> 7;          // / NC
    int c = blk & (NC - 1);
    int t0 = c * CHUNK;
    int tid = threadIdx.x;     // 0..63

    __shared__ float2 s_al[CHUNK * MM];   // (a, 1-a)

    if (tid < CHUNK) {
        int t = t0 + tid;
        float dt = 0.0f;
        if (t > 0)
            dt = fmaxf(delta[b * TT + t] - delta[b * TT + t - 1], 0.0f);
#pragma unroll
        for (int m = 0; m < MM; m++) {
            float a = expf(-dt / tau[m]);
            s_al[tid * MM + m] = make_float2(a, 1.0f - a);
        }
    }
    __syncthreads();

    if (tid < MM) {
        float p = 1.0f;
#pragma unroll
        for (int t = 0; t < CHUNK; t++) p *= s_al[t * MM + tid].x;
        g_A[(b * NC + c) * MM + tid] = p;
    }

    const float4* xp = (const float4*)x + ((size_t)b * TT + t0) * D4 + tid;

    float4 s[MM];
#pragma unroll
    for (int m = 0; m < MM; m++) s[m] = make_float4(0.f, 0.f, 0.f, 0.f);

#pragma unroll 4
    for (int t = 0; t < CHUNK; t++) {
        float4 xv = __ldg(xp + (size_t)t * D4);
#pragma unroll
        for (int m = 0; m < MM; m++) {
            float2 al = s_al[t * MM + m];
            s[m].x = fmaf(al.x, s[m].x, al.y * xv.x);
            s[m].y = fmaf(al.x, s[m].y, al.y * xv.y);
            s[m].z = fmaf(al.x, s[m].z, al.y * xv.z);
            s[m].w = fmaf(al.x, s[m].w, al.y * xv.w);
        }
    }

    float4* Lp = (float4*)g_L + (size_t)(b * NC + c) * RPB + tid;
#pragma unroll
    for (int m = 0; m < MM; m++) Lp[m * D4] = s[m];
}

// ---------------------------------------------------------------------------
// Kernel 2: sequential exclusive scan across chunks per (b, m, d4).
//   sinit[c] = s;  s = A[c]*s + L[c]
// ---------------------------------------------------------------------------
__global__ __launch_bounds__(256) void k_scan()
{
    int idx = blockIdx.x * 256 + threadIdx.x;   // 0 .. B*M*D4-1 = 4095
    int b = idx >> 9;          // / RPB
    int r = idx & (RPB - 1);
    int m = r >> 6;            // / D4

    const float4* Lp = (const float4*)g_L;
    float4* Sp = (float4*)g_S;

    float4 s = make_float4(0.f, 0.f, 0.f, 0.f);
#pragma unroll 8
    for (int c = 0; c < NC; c++) {
        size_t off = (size_t)(b * NC + c) * RPB + r;
        float4 L = Lp[off];
        float  A = g_A[(b * NC + c) * MM + m];
        Sp[off] = s;
        s.x = fmaf(A, s.x, L.x);
        s.y = fmaf(A, s.y, L.y);
        s.z = fmaf(A, s.z, L.z);
        s.w = fmaf(A, s.w, L.w);
    }
}

// ---------------------------------------------------------------------------
// Kernel 3: replay each chunk from its initial state, write all outputs.
// Block = (b, c). 64 threads, float4 per m per step (coalesced STG.128).
// out[((b*T+t)*M + m)*D + d]
// ---------------------------------------------------------------------------
__global__ __launch_bounds__(64) void k_final(
    const float* __restrict__ x, const float* __restrict__ delta,
    const float* __restrict__ tau, float* __restrict__ out)
{
    int blk = blockIdx.x;
    int b = blk >> 7;
    int c = blk & (NC - 1);
    int t0 = c * CHUNK;
    int tid = threadIdx.x;

    __shared__ float2 s_al[CHUNK * MM];

    if (tid < CHUNK) {
        int t = t0 + tid;
        float dt = 0.0f;
        if (t > 0)
            dt = fmaxf(delta[b * TT + t] - delta[b * TT + t - 1], 0.0f);
#pragma unroll
        for (int m = 0; m < MM; m++) {
            float a = expf(-dt / tau[m]);
            s_al[tid * MM + m] = make_float2(a, 1.0f - a);
        }
    }
    __syncthreads();

    // load chunk initial state
    size_t roff = (size_t)(b * NC + c) * RPB + tid;
    float4 s[MM];
#pragma unroll
    for (int m = 0; m < MM; m++) s[m] = ((const float4*)g_S)[roff + m * D4];

    const float4* xp = (const float4*)x + ((size_t)b * TT + t0) * D4 + tid;
    float4* op = (float4*)out + ((size_t)(b * TT + t0) * MM) * D4 + tid;

#pragma unroll 4
    for (int t = 0; t < CHUNK; t++) {
        float4 xv = __ldg(xp + (size_t)t * D4);
#pragma unroll
        for (int m = 0; m < MM; m++) {
            float2 al = s_al[t * MM + m];
            s[m].x = fmaf(al.x, s[m].x, al.y * xv.x);
            s[m].y = fmaf(al.x, s[m].y, al.y * xv.y);
            s[m].z = fmaf(al.x, s[m].z, al.y * xv.z);
            s[m].w = fmaf(al.x, s[m].w, al.y * xv.w);
            op[(size_t)t * (MM * D4) + m * D4] = s[m];
        }
    }
}

extern "C" void kernel_launch(void* const* d_in, const int* in_sizes, int n_in,
                              void* d_out, int out_size)
{
    const float* x     = (const float*)d_in[0];
    const float* delta = (const float*)d_in[1];
    const float* tau   = (const float*)d_in[2];
    float* out = (float*)d_out;

    k_locals<<<BB * NC, 64>>>(x, delta, tau);
    k_scan<<<(BB * MM * D4) / 256, 256>>>();
    k_final<<<BB * NC, 64>>>(x, delta, tau, out);
}

// round 3
// speedup vs baseline: 1.1462x; 1.1462x over previous
#include <cuda_runtime.h>
#include <cuda_bf16.h>
#include <math.h>

// Problem constants
#define BB   8
#define TT   4096
#define DD   256
#define MM   8
#define CHUNK 32
#define NC   (TT / CHUNK)      // 128 chunks along T
#define D4   (DD / 4)          // 64 float4 groups per row
#define RPB  (MM * D4)         // 512 float4 "r" slots per (b,c)

// Scratch (static device allocations — no runtime alloc)
__device__ float g_L[(size_t)BB * NC * MM * DD];   // chunk-local final states, 8 MB
__device__ float g_S[(size_t)BB * NC * MM * DD];   // chunk initial states,     8 MB
__device__ float g_A[BB * NC * MM];                // chunk decay products

// ---------------------------------------------------------------------------
// Kernel 1: per-chunk local recurrence (s starts at 0), store L and A.
// Block = (b, c). 256 threads: tid = g*64 + d4, thread owns m = {2g, 2g+1}.
// ---------------------------------------------------------------------------
__global__ __launch_bounds__(256) void k_locals(
    const float* __restrict__ x, const float* __restrict__ delta,
    const float* __restrict__ tau)
{
    int blk = blockIdx.x;
    int b = blk >> 7;          // / NC
    int c = blk & (NC - 1);
    int t0 = c * CHUNK;
    int tid = threadIdx.x;
    int d4 = tid & 63;
    int g  = tid >> 6;         // 0..3
    int m0 = g * 2;
    int m1 = m0 + 1;

    __shared__ float2 s_al[CHUNK * MM];   // (a, 1-a)

    if (tid < CHUNK) {
        int t = t0 + tid;
        float dt = 0.0f;
        if (t > 0)
            dt = fmaxf(delta[b * TT + t] - delta[b * TT + t - 1], 0.0f);
#pragma unroll
        for (int m = 0; m < MM; m++) {
            float a = expf(-dt / tau[m]);
            s_al[tid * MM + m] = make_float2(a, 1.0f - a);
        }
    }
    __syncthreads();

    if (tid < MM) {
        float p = 1.0f;
#pragma unroll
        for (int t = 0; t < CHUNK; t++) p *= s_al[t * MM + tid].x;
        g_A[(b * NC + c) * MM + tid] = p;
    }

    const float4* xp = (const float4*)x + ((size_t)b * TT + t0) * D4 + d4;

    float4 s0 = make_float4(0.f, 0.f, 0.f, 0.f);
    float4 s1 = make_float4(0.f, 0.f, 0.f, 0.f);

#pragma unroll 8
    for (int t = 0; t < CHUNK; t++) {
        float4 xv = __ldg(xp + (size_t)t * D4);
        float2 a0 = s_al[t * MM + m0];
        float2 a1 = s_al[t * MM + m1];
        s0.x = fmaf(a0.x, s0.x, a0.y * xv.x);
        s0.y = fmaf(a0.x, s0.y, a0.y * xv.y);
        s0.z = fmaf(a0.x, s0.z, a0.y * xv.z);
        s0.w = fmaf(a0.x, s0.w, a0.y * xv.w);
        s1.x = fmaf(a1.x, s1.x, a1.y * xv.x);
        s1.y = fmaf(a1.x, s1.y, a1.y * xv.y);
        s1.z = fmaf(a1.x, s1.z, a1.y * xv.z);
        s1.w = fmaf(a1.x, s1.w, a1.y * xv.w);
    }

    float4* Lp = (float4*)g_L + (size_t)(b * NC + c) * RPB + d4;
    Lp[m0 * D4] = s0;
    Lp[m1 * D4] = s1;
}

// ---------------------------------------------------------------------------
// Kernel 2: sequential exclusive scan across chunks per (b, m, d4).
//   sinit[c] = s;  s = A[c]*s + L[c]
// 64 blocks x 64 threads -> spread the 4096 chains over more SMs.
// ---------------------------------------------------------------------------
__global__ __launch_bounds__(64) void k_scan()
{
    int idx = blockIdx.x * 64 + threadIdx.x;    // 0 .. B*M*D4-1 = 4095
    int b = idx >> 9;          // / RPB
    int r = idx & (RPB - 1);
    int m = r >> 6;            // / D4

    const float4* Lp = (const float4*)g_L;
    float4* Sp = (float4*)g_S;

    float4 s = make_float4(0.f, 0.f, 0.f, 0.f);
#pragma unroll 8
    for (int c = 0; c < NC; c++) {
        size_t off = (size_t)(b * NC + c) * RPB + r;
        float4 L = __ldg(Lp + off);
        float  A = __ldg(&g_A[(b * NC + c) * MM + m]);
        Sp[off] = s;
        s.x = fmaf(A, s.x, L.x);
        s.y = fmaf(A, s.y, L.y);
        s.z = fmaf(A, s.z, L.z);
        s.w = fmaf(A, s.w, L.w);
    }
}

// ---------------------------------------------------------------------------
// Kernel 3: replay each chunk from its initial state, write all outputs.
// Block = (b, c). 256 threads: tid = g*64 + d4, thread owns m = {2g, 2g+1}.
// out[((b*T+t)*M + m)*D + d], streaming stores (keep x resident in L2).
// ---------------------------------------------------------------------------
__global__ __launch_bounds__(256) void k_final(
    const float* __restrict__ x, const float* __restrict__ delta,
    const float* __restrict__ tau, float* __restrict__ out)
{
    int blk = blockIdx.x;
    int b = blk >> 7;
    int c = blk & (NC - 1);
    int t0 = c * CHUNK;
    int tid = threadIdx.x;
    int d4 = tid & 63;
    int g  = tid >> 6;
    int m0 = g * 2;
    int m1 = m0 + 1;

    __shared__ float2 s_al[CHUNK * MM];

    if (tid < CHUNK) {
        int t = t0 + tid;
        float dt = 0.0f;
        if (t > 0)
            dt = fmaxf(delta[b * TT + t] - delta[b * TT + t - 1], 0.0f);
#pragma unroll
        for (int m = 0; m < MM; m++) {
            float a = expf(-dt / tau[m]);
            s_al[tid * MM + m] = make_float2(a, 1.0f - a);
        }
    }
    __syncthreads();

    // load chunk initial state
    size_t roff = (size_t)(b * NC + c) * RPB + d4;
    float4 s0 = ((const float4*)g_S)[roff + m0 * D4];
    float4 s1 = ((const float4*)g_S)[roff + m1 * D4];

    const float4* xp = (const float4*)x + ((size_t)b * TT + t0) * D4 + d4;
    float4* op = (float4*)out + ((size_t)(b * TT + t0) * MM) * D4 + d4;

#pragma unroll 8
    for (int t = 0; t < CHUNK; t++) {
        float4 xv = __ldg(xp + (size_t)t * D4);
        float2 a0 = s_al[t * MM + m0];
        float2 a1 = s_al[t * MM + m1];
        s0.x = fmaf(a0.x, s0.x, a0.y * xv.x);
        s0.y = fmaf(a0.x, s0.y, a0.y * xv.y);
        s0.z = fmaf(a0.x, s0.z, a0.y * xv.z);
        s0.w = fmaf(a0.x, s0.w, a0.y * xv.w);
        s1.x = fmaf(a1.x, s1.x, a1.y * xv.x);
        s1.y = fmaf(a1.x, s1.y, a1.y * xv.y);
        s1.z = fmaf(a1.x, s1.z, a1.y * xv.z);
        s1.w = fmaf(a1.x, s1.w, a1.y * xv.w);
        __stcs(op + (size_t)t * RPB + m0 * D4, s0);
        __stcs(op + (size_t)t * RPB + m1 * D4, s1);
    }
}

extern "C" void kernel_launch(void* const* d_in, const int* in_sizes, int n_in,
                              void* d_out, int out_size)
{
    const float* x     = (const float*)d_in[0];
    const float* delta = (const float*)d_in[1];
    const float* tau   = (const float*)d_in[2];
    float* out = (float*)d_out;

    k_locals<<<BB * NC, 256>>>(x, delta, tau);
    k_scan<<<64, 64>>>();
    k_final<<<BB * NC, 256>>>(x, delta, tau, out);
}

// round 4
// speedup vs baseline: 1.2443x; 1.0856x over previous
#include <cuda_runtime.h>
#include <cuda_bf16.h>
#include <math.h>

// Problem constants
#define BB   8
#define TT   4096
#define DD   256
#define MM   8
#define CHUNK 32
#define NC   (TT / CHUNK)      // 128 chunks along T
#define D4   (DD / 4)          // 64 float4 groups per row
#define RPB  (MM * D4)         // 512 float4 "r" slots per (b,c)

// Scratch (static device allocations — no runtime alloc)
__device__ float g_L[(size_t)BB * NC * MM * DD];   // chunk-local final states, 8 MB
__device__ float g_S[(size_t)BB * NC * MM * DD];   // chunk initial states,     8 MB
__device__ float g_A[BB * NC * MM];                // chunk decay products

// ---------------------------------------------------------------------------
// Kernel 1: per-chunk local recurrence (s starts at 0), store L and A.
// Block = (b, c). 256 threads: tid = g*64 + d4, thread owns m = {2g, 2g+1}.
// x chunk staged through smem once (no 4x LDG duplication across m-groups).
// ---------------------------------------------------------------------------
__global__ __launch_bounds__(256) void k_locals(
    const float* __restrict__ x, const float* __restrict__ delta,
    const float* __restrict__ tau)
{
    int blk = blockIdx.x;
    int b = blk >> 7;          // / NC
    int c = blk & (NC - 1);
    int t0 = c * CHUNK;
    int tid = threadIdx.x;
    int d4 = tid & 63;
    int g  = tid >> 6;         // 0..3
    int m0 = g * 2;
    int m1 = m0 + 1;

    __shared__ float2 s_al[CHUNK * MM];     // (a, 1-a)
    __shared__ float4 s_x[CHUNK * D4];      // 32 KB x tile

    if (tid < CHUNK) {
        int t = t0 + tid;
        float dt = 0.0f;
        if (t > 0)
            dt = fmaxf(delta[b * TT + t] - delta[b * TT + t - 1], 0.0f);
#pragma unroll
        for (int m = 0; m < MM; m++) {
            float a = expf(-dt / tau[m]);
            s_al[tid * MM + m] = make_float2(a, 1.0f - a);
        }
    }

    // cooperative coalesced load of the x chunk (8 independent LDG.128/thread)
    {
        const float4* xp = (const float4*)x + ((size_t)b * TT + t0) * D4;
#pragma unroll
        for (int i = 0; i < (CHUNK * D4) / 256; i++)
            s_x[i * 256 + tid] = __ldg(xp + i * 256 + tid);
    }
    __syncthreads();

    if (tid < MM) {
        float p = 1.0f;
#pragma unroll
        for (int t = 0; t < CHUNK; t++) p *= s_al[t * MM + tid].x;
        g_A[(b * NC + c) * MM + tid] = p;
    }

    float4 s0 = make_float4(0.f, 0.f, 0.f, 0.f);
    float4 s1 = make_float4(0.f, 0.f, 0.f, 0.f);

#pragma unroll 8
    for (int t = 0; t < CHUNK; t++) {
        float4 xv = s_x[t * D4 + d4];
        float2 a0 = s_al[t * MM + m0];
        float2 a1 = s_al[t * MM + m1];
        s0.x = fmaf(a0.x, s0.x, a0.y * xv.x);
        s0.y = fmaf(a0.x, s0.y, a0.y * xv.y);
        s0.z = fmaf(a0.x, s0.z, a0.y * xv.z);
        s0.w = fmaf(a0.x, s0.w, a0.y * xv.w);
        s1.x = fmaf(a1.x, s1.x, a1.y * xv.x);
        s1.y = fmaf(a1.x, s1.y, a1.y * xv.y);
        s1.z = fmaf(a1.x, s1.z, a1.y * xv.z);
        s1.w = fmaf(a1.x, s1.w, a1.y * xv.w);
    }

    float4* Lp = (float4*)g_L + (size_t)(b * NC + c) * RPB + d4;
    Lp[m0 * D4] = s0;
    Lp[m1 * D4] = s1;
}

// ---------------------------------------------------------------------------
// Kernel 2: sequential exclusive scan across chunks per (b, m, d4).
//   sinit[c] = s;  s = A[c]*s + L[c]
// ---------------------------------------------------------------------------
__global__ __launch_bounds__(64) void k_scan()
{
    int idx = blockIdx.x * 64 + threadIdx.x;    // 0 .. B*M*D4-1 = 4095
    int b = idx >> 9;          // / RPB
    int r = idx & (RPB - 1);
    int m = r >> 6;            // / D4

    const float4* Lp = (const float4*)g_L;
    float4* Sp = (float4*)g_S;

    float4 s = make_float4(0.f, 0.f, 0.f, 0.f);
#pragma unroll 8
    for (int c = 0; c < NC; c++) {
        size_t off = (size_t)(b * NC + c) * RPB + r;
        float4 L = __ldg(Lp + off);
        float  A = __ldg(&g_A[(b * NC + c) * MM + m]);
        Sp[off] = s;
        s.x = fmaf(A, s.x, L.x);
        s.y = fmaf(A, s.y, L.y);
        s.z = fmaf(A, s.z, L.z);
        s.w = fmaf(A, s.w, L.w);
    }
}

// ---------------------------------------------------------------------------
// Kernel 3: replay each chunk from its initial state, write all outputs.
// Block = (b, c). 256 threads: tid = g*64 + d4, thread owns m = {2g, 2g+1}.
// x staged in smem; streaming stores for the 256 MB output.
// ---------------------------------------------------------------------------
__global__ __launch_bounds__(256) void k_final(
    const float* __restrict__ x, const float* __restrict__ delta,
    const float* __restrict__ tau, float* __restrict__ out)
{
    int blk = blockIdx.x;
    int b = blk >> 7;
    int c = blk & (NC - 1);
    int t0 = c * CHUNK;
    int tid = threadIdx.x;
    int d4 = tid & 63;
    int g  = tid >> 6;
    int m0 = g * 2;
    int m1 = m0 + 1;

    __shared__ float2 s_al[CHUNK * MM];
    __shared__ float4 s_x[CHUNK * D4];      // 32 KB x tile

    if (tid < CHUNK) {
        int t = t0 + tid;
        float dt = 0.0f;
        if (t > 0)
            dt = fmaxf(delta[b * TT + t] - delta[b * TT + t - 1], 0.0f);
#pragma unroll
        for (int m = 0; m < MM; m++) {
            float a = expf(-dt / tau[m]);
            s_al[tid * MM + m] = make_float2(a, 1.0f - a);
        }
    }

    {
        const float4* xp = (const float4*)x + ((size_t)b * TT + t0) * D4;
#pragma unroll
        for (int i = 0; i < (CHUNK * D4) / 256; i++)
            s_x[i * 256 + tid] = __ldg(xp + i * 256 + tid);
    }

    // load chunk initial state (overlaps with smem fill)
    size_t roff = (size_t)(b * NC + c) * RPB + d4;
    float4 s0 = ((const float4*)g_S)[roff + m0 * D4];
    float4 s1 = ((const float4*)g_S)[roff + m1 * D4];

    __syncthreads();

    float4* op = (float4*)out + ((size_t)(b * TT + t0) * MM) * D4 + d4;

#pragma unroll 8
    for (int t = 0; t < CHUNK; t++) {
        float4 xv = s_x[t * D4 + d4];
        float2 a0 = s_al[t * MM + m0];
        float2 a1 = s_al[t * MM + m1];
        s0.x = fmaf(a0.x, s0.x, a0.y * xv.x);
        s0.y = fmaf(a0.x, s0.y, a0.y * xv.y);
        s0.z = fmaf(a0.x, s0.z, a0.y * xv.z);
        s0.w = fmaf(a0.x, s0.w, a0.y * xv.w);
        s1.x = fmaf(a1.x, s1.x, a1.y * xv.x);
        s1.y = fmaf(a1.x, s1.y, a1.y * xv.y);
        s1.z = fmaf(a1.x, s1.z, a1.y * xv.z);
        s1.w = fmaf(a1.x, s1.w, a1.y * xv.w);
        __stcs(op + (size_t)t * RPB + m0 * D4, s0);
        __stcs(op + (size_t)t * RPB + m1 * D4, s1);
    }
}

extern "C" void kernel_launch(void* const* d_in, const int* in_sizes, int n_in,
                              void* d_out, int out_size)
{
    const float* x     = (const float*)d_in[0];
    const float* delta = (const float*)d_in[1];
    const float* tau   = (const float*)d_in[2];
    float* out = (float*)d_out;

    k_locals<<<BB * NC, 256>>>(x, delta, tau);
    k_scan<<<64, 64>>>();
    k_final<<<BB * NC, 256>>>(x, delta, tau, out);
}